// round 15
// baseline (speedup 1.0000x reference)
#include <cuda_runtime.h>
#include <cuda_fp16.h>
#include <cstdint>

// Single-head causal attention, B=4096, T=128, C=64, H=64, fp32 I/O.
// Round 14: 2 row-tiles per warp + 2 batches per CTA (grid 2048).
// Warp (s = wid&3) owns tiles {s, 7-s} of batch (2*blk + wid>>2):
//  - proj B-frag loads serve 32 rows (-50% proj ldsm/batch)
//  - flash x/V block loads shared by both tiles (-28% flash ldsm/batch)
//  - SMSP MMA work stays exactly balanced (9 blocks each)
// No-max softmax in log2 domain, 1-pass fp16 GEMMs, direct-STG epilogue.

namespace {

constexpr int Tn = 128, Cn = 64, Hn = 64;

// fp16 tiles, 144-byte row stride (conflict-free ldmatrix).
constexpr int OFF_XH = 0;         // 2 x 18432 (batch 0, batch 1)
constexpr int OFF_MT = 36864;     // M^T fp16 (9216)
constexpr int OFF_WV = 46080;     // Wv fp16 (9216)
constexpr int OFF_V  = 55296;     // 2 x 18432 (batch 0, batch 1)
constexpr int SMEM_TOTAL = 92160; // 90KB -> 2 CTAs/SM

__device__ float g_MT[64 * 64];   // MT[c'][c] = 0.125*log2e * sum_h Wq[h][c]*Wk[h][c']

__device__ __forceinline__ uint32_t smem_u32(const void* p) {
  uint32_t a;
  asm("{ .reg .u64 t; cvta.to.shared.u64 t, %1; cvt.u32.u64 %0, t; }"
      : "=r"(a) : "l"(p));
  return a;
}
__device__ __forceinline__ float ex2(float x) {
  float r;
  asm("ex2.approx.f32 %0, %1;" : "=f"(r) : "f"(x));
  return r;
}
__device__ __forceinline__ void ldsm4(uint32_t* r, uint32_t a) {
  asm volatile("ldmatrix.sync.aligned.m8n8.x4.shared.b16 {%0,%1,%2,%3}, [%4];"
               : "=r"(r[0]), "=r"(r[1]), "=r"(r[2]), "=r"(r[3]) : "r"(a));
}
__device__ __forceinline__ void ldsm4t(uint32_t* r, uint32_t a) {
  asm volatile("ldmatrix.sync.aligned.m8n8.x4.trans.shared.b16 {%0,%1,%2,%3}, [%4];"
               : "=r"(r[0]), "=r"(r[1]), "=r"(r[2]), "=r"(r[3]) : "r"(a));
}
__device__ __forceinline__ void mma_f16(float* d, const uint32_t* a,
                                        uint32_t b0, uint32_t b1) {
  asm volatile(
      "mma.sync.aligned.m16n8k16.row.col.f32.f16.f16.f32 "
      "{%0,%1,%2,%3}, {%4,%5,%6,%7}, {%8,%9}, {%0,%1,%2,%3};"
      : "+f"(d[0]), "+f"(d[1]), "+f"(d[2]), "+f"(d[3])
      : "r"(a[0]), "r"(a[1]), "r"(a[2]), "r"(a[3]), "r"(b0), "r"(b1));
}
__device__ __forceinline__ uint32_t pack2h(float a, float b) {
  __half2 h2 = __floats2half2_rn(a, b);
  return *reinterpret_cast<uint32_t*>(&h2);
}

// ---- pre-kernel: MT[c'][c] = 0.125*log2e * sum_h Wq[h][c]*Wk[h][c'] ----
__global__ void mt_kernel(const float* __restrict__ Wq,
                          const float* __restrict__ Wk) {
  int i = blockIdx.x * 256 + threadIdx.x;   // 16 blocks x 256 = 4096
  int cp = i >> 6, c = i & 63;
  float s = 0.f;
#pragma unroll 8
  for (int h = 0; h < 64; ++h) s += Wq[h * 64 + c] * Wk[h * 64 + cp];
  g_MT[i] = 0.18033688011112042f * s;   // 0.125 * log2(e)
}

__global__ void __launch_bounds__(256, 2)
attn_hmma_kernel(const float* __restrict__ x,
                 const float* __restrict__ Wv,
                 float* __restrict__ out) {
  extern __shared__ char sm[];
  const uint32_t sb = smem_u32(sm);
  const int tid  = threadIdx.x;
  const int w    = tid >> 5;
  const int lane = tid & 31;
  const int bw   = w >> 2;       // batch within CTA (0/1)
  const int s    = w & 3;        // SMSP index / tile selector
  const int tA   = s, tB = 7 - s;
  const int m0A  = tA * 16, m0B = tB * 16;

  const int arow = lane & 15;
  const int acol = (lane >> 4) * 8;
  const int brow = (lane & 7) + ((lane >= 16) ? 8 : 0);
  const int bk   = ((lane >> 3) & 1) * 8;
  const int trow = (lane & 7) | (((lane >> 3) & 1) << 3);
  const int tcol = (lane >= 16) ? 8 : 0;
  const int qr   = lane >> 2;
  const int qc   = (lane & 3) * 2;

  // ---------------- phase 0: stage x (2 batches), MT, Wv as fp16 ----------
  {
#pragma unroll
    for (int bb = 0; bb < 2; ++bb) {
      const float4* xg = reinterpret_cast<const float4*>(
          x + (size_t)(blockIdx.x * 2 + bb) * Tn * Cn);
#pragma unroll
      for (int it = 0; it < 8; ++it) {
        int gi = it * 256 + tid;
        float4 v = xg[gi];
        int t = gi >> 4, c0 = (gi & 15) << 2;
        uint32_t o = (uint32_t)(t * 144 + c0 * 2);
        *reinterpret_cast<uint2*>(sm + OFF_XH + bb * 18432 + o) =
            make_uint2(pack2h(v.x, v.y), pack2h(v.z, v.w));
      }
    }
    const float4* mg = reinterpret_cast<const float4*>(g_MT);
#pragma unroll
    for (int it = 0; it < 4; ++it) {
      int gi = it * 256 + tid;
      float4 v = mg[gi];
      int h = gi >> 4, c0 = (gi & 15) << 2;
      uint32_t o = (uint32_t)(h * 144 + c0 * 2);
      *reinterpret_cast<uint2*>(sm + OFF_MT + o) =
          make_uint2(pack2h(v.x, v.y), pack2h(v.z, v.w));
    }
    const float4* wg = reinterpret_cast<const float4*>(Wv);
#pragma unroll
    for (int it = 0; it < 4; ++it) {
      int gi = it * 256 + tid;
      float4 v = wg[gi];
      int h = gi >> 4, c0 = (gi & 15) << 2;
      uint32_t o = (uint32_t)(h * 144 + c0 * 2);
      *reinterpret_cast<uint2*>(sm + OFF_WV + o) =
          make_uint2(pack2h(v.x, v.y), pack2h(v.z, v.w));
    }
  }
  __syncthreads();

  const uint32_t xbase = sb + OFF_XH + bw * 18432;
  const uint32_t vbase = sb + OFF_V  + bw * 18432;

  // ---------------- x A-frags for both tiles ----------------
  uint32_t xhA[4][4], xhB[4][4];
#pragma unroll
  for (int kk = 0; kk < 4; ++kk) {
    uint32_t oc = (uint32_t)((kk * 16 + acol) * 2);
    ldsm4(xhA[kk], xbase + (uint32_t)((m0A + arow) * 144) + oc);
    ldsm4(xhB[kk], xbase + (uint32_t)((m0B + arow) * 144) + oc);
  }

  float accA[8][4], accB[8][4];
  // 1-pass GEMM for both tiles: one B-frag load serves 32 rows.
  auto proj2 = [&](int wbase) {
#pragma unroll
    for (int j = 0; j < 8; ++j)
#pragma unroll
      for (int e = 0; e < 4; ++e) { accA[j][e] = 0.f; accB[j][e] = 0.f; }
#pragma unroll
    for (int kk = 0; kk < 4; ++kk) {
#pragma unroll
      for (int up = 0; up < 2; ++up) {
        uint32_t bh0[4], bh1[4];
        uint32_t o0 = (uint32_t)((16 * (2 * up)     + brow) * 144 + (kk * 16 + bk) * 2);
        uint32_t o1 = (uint32_t)((16 * (2 * up + 1) + brow) * 144 + (kk * 16 + bk) * 2);
        ldsm4(bh0, sb + wbase + o0);
        ldsm4(bh1, sb + wbase + o1);
        mma_f16(accA[4 * up],     xhA[kk], bh0[0], bh0[1]);
        mma_f16(accA[4 * up + 1], xhA[kk], bh0[2], bh0[3]);
        mma_f16(accA[4 * up + 2], xhA[kk], bh1[0], bh1[1]);
        mma_f16(accA[4 * up + 3], xhA[kk], bh1[2], bh1[3]);
        mma_f16(accB[4 * up],     xhB[kk], bh0[0], bh0[1]);
        mma_f16(accB[4 * up + 1], xhB[kk], bh0[2], bh0[3]);
        mma_f16(accB[4 * up + 2], xhB[kk], bh1[0], bh1[1]);
        mma_f16(accB[4 * up + 3], xhB[kk], bh1[2], bh1[3]);
      }
    }
  };

  // V = x @ Wv^T first (frees acc for MT proj), spill to V smem.
  proj2(OFF_WV);
  {
    const int rA = m0A + qr, rB = m0B + qr;
#pragma unroll
    for (int j = 0; j < 8; ++j) {
      int h = j * 8 + qc;
      *reinterpret_cast<uint32_t*>(sm + OFF_V + bw * 18432 + rA * 144 + h * 2) =
          pack2h(accA[j][0], accA[j][1]);
      *reinterpret_cast<uint32_t*>(sm + OFF_V + bw * 18432 + (rA + 8) * 144 + h * 2) =
          pack2h(accA[j][2], accA[j][3]);
      *reinterpret_cast<uint32_t*>(sm + OFF_V + bw * 18432 + rB * 144 + h * 2) =
          pack2h(accB[j][0], accB[j][1]);
      *reinterpret_cast<uint32_t*>(sm + OFF_V + bw * 18432 + (rB + 8) * 144 + h * 2) =
          pack2h(accB[j][2], accB[j][3]);
    }
  }
  // q = x @ MT^T (scale+log2e folded) -> A-frags fp16 for both tiles
  proj2(OFF_MT);
  uint32_t qhA[4][4], qhB[4][4];
#pragma unroll
  for (int kk = 0; kk < 4; ++kk) {
    qhA[kk][0] = pack2h(accA[2 * kk][0],     accA[2 * kk][1]);
    qhA[kk][1] = pack2h(accA[2 * kk][2],     accA[2 * kk][3]);
    qhA[kk][2] = pack2h(accA[2 * kk + 1][0], accA[2 * kk + 1][1]);
    qhA[kk][3] = pack2h(accA[2 * kk + 1][2], accA[2 * kk + 1][3]);
    qhB[kk][0] = pack2h(accB[2 * kk][0],     accB[2 * kk][1]);
    qhB[kk][1] = pack2h(accB[2 * kk][2],     accB[2 * kk][3]);
    qhB[kk][2] = pack2h(accB[2 * kk + 1][0], accB[2 * kk + 1][1]);
    qhB[kk][3] = pack2h(accB[2 * kk + 1][2], accB[2 * kk + 1][3]);
  }
  __syncthreads();          // V spills visible to all warps of this batch

  // ---------------- flash loop (shared block loads, 2 tiles) ---------------
  float accOA[8][4], accOB[8][4];
#pragma unroll
  for (int j = 0; j < 8; ++j)
#pragma unroll
    for (int e = 0; e < 4; ++e) { accOA[j][e] = 0.f; accOB[j][e] = 0.f; }
  float pAA = 0.f, pBA = 0.f, pAB = 0.f, pBB = 0.f;

  uint32_t xo = xbase + (uint32_t)(brow * 144 + bk * 2);
  uint32_t vo = vbase + (uint32_t)(trow * 144 + tcol * 2);

  uint32_t b0[4], b1[4], b2[4], b3[4], v0[4], v1[4], v2[4], v3[4];
  auto load_b = [&]() {
    ldsm4(b0, xo); ldsm4(b1, xo + 32); ldsm4(b2, xo + 64); ldsm4(b3, xo + 96);
  };
  auto load_v = [&]() {
    ldsm4t(v0, vo); ldsm4t(v1, vo + 32); ldsm4t(v2, vo + 64); ldsm4t(v3, vo + 96);
  };
  auto do_s = [&](const uint32_t (&qh)[4][4], float (&sf)[2][4]) {
#pragma unroll
    for (int j = 0; j < 2; ++j)
#pragma unroll
      for (int e = 0; e < 4; ++e) sf[j][e] = 0.f;
    mma_f16(sf[0], qh[0], b0[0], b0[1]);
    mma_f16(sf[1], qh[0], b0[2], b0[3]);
    mma_f16(sf[0], qh[1], b1[0], b1[1]);
    mma_f16(sf[1], qh[1], b1[2], b1[3]);
    mma_f16(sf[0], qh[2], b2[0], b2[1]);
    mma_f16(sf[1], qh[2], b2[2], b2[3]);
    mma_f16(sf[0], qh[3], b3[0], b3[1]);
    mma_f16(sf[1], qh[3], b3[2], b3[3]);
  };
  auto do_exp_full = [&](const float (&sf)[2][4], float& pA, float& pB,
                         uint32_t* ph) {
    float e00 = ex2(sf[0][0]), e01 = ex2(sf[0][1]);
    float e10 = ex2(sf[1][0]), e11 = ex2(sf[1][1]);
    float e02 = ex2(sf[0][2]), e03 = ex2(sf[0][3]);
    float e12 = ex2(sf[1][2]), e13 = ex2(sf[1][3]);
    pA += e00 + e01 + e10 + e11;
    pB += e02 + e03 + e12 + e13;
    ph[0] = pack2h(e00, e01); ph[1] = pack2h(e02, e03);
    ph[2] = pack2h(e10, e11); ph[3] = pack2h(e12, e13);
  };
  auto do_exp_diag = [&](const float (&sf)[2][4], float& pA, float& pB,
                         uint32_t* ph) {
    float e00 = (qc     <= qr)     ? ex2(sf[0][0]) : 0.f;
    float e01 = (qc + 1 <= qr)     ? ex2(sf[0][1]) : 0.f;
    float e10 = (8 + qc     <= qr) ? ex2(sf[1][0]) : 0.f;
    float e11 = (8 + qc + 1 <= qr) ? ex2(sf[1][1]) : 0.f;
    float e02 = (qc     <= qr + 8) ? ex2(sf[0][2]) : 0.f;
    float e03 = (qc + 1 <= qr + 8) ? ex2(sf[0][3]) : 0.f;
    float e12 = (8 + qc     <= qr + 8) ? ex2(sf[1][2]) : 0.f;
    float e13 = (8 + qc + 1 <= qr + 8) ? ex2(sf[1][3]) : 0.f;
    pA += e00 + e01 + e10 + e11;
    pB += e02 + e03 + e12 + e13;
    ph[0] = pack2h(e00, e01); ph[1] = pack2h(e02, e03);
    ph[2] = pack2h(e10, e11); ph[3] = pack2h(e12, e13);
  };
  auto do_pv = [&](float (&accO)[8][4], const uint32_t* ph) {
    mma_f16(accO[0], ph, v0[0], v0[1]);
    mma_f16(accO[1], ph, v0[2], v0[3]);
    mma_f16(accO[2], ph, v1[0], v1[1]);
    mma_f16(accO[3], ph, v1[2], v1[3]);
    mma_f16(accO[4], ph, v2[0], v2[1]);
    mma_f16(accO[5], ph, v2[2], v2[3]);
    mma_f16(accO[6], ph, v3[0], v3[1]);
    mma_f16(accO[7], ph, v3[2], v3[3]);
  };

  float sf[2][4];
  uint32_t phA[4], phB[4];

  // kb = 0 .. s-1 : tile A full + tile B full (shared loads)
  for (int kb = 0; kb < s; ++kb) {
    load_b();
    do_s(qhA, sf); do_exp_full(sf, pAA, pBA, phA);
    do_s(qhB, sf); do_exp_full(sf, pAB, pBB, phB);
    load_v();
    do_pv(accOA, phA);
    do_pv(accOB, phB);
    xo += 2304; vo += 2304;
  }
  // kb = s : tile A diagonal + tile B full
  {
    load_b();
    do_s(qhA, sf); do_exp_diag(sf, pAA, pBA, phA);
    do_s(qhB, sf); do_exp_full(sf, pAB, pBB, phB);
    load_v();
    do_pv(accOA, phA);
    do_pv(accOB, phB);
    xo += 2304; vo += 2304;
  }
  // kb = s+1 .. 6-s : tile B full only
  for (int kb = s + 1; kb < 7 - s; ++kb) {
    load_b();
    do_s(qhB, sf); do_exp_full(sf, pAB, pBB, phB);
    load_v();
    do_pv(accOB, phB);
    xo += 2304; vo += 2304;
  }
  // kb = 7-s : tile B diagonal
  {
    load_b();
    do_s(qhB, sf); do_exp_diag(sf, pAB, pBB, phB);
    load_v();
    do_pv(accOB, phB);
  }

  pAA += __shfl_xor_sync(0xffffffffu, pAA, 1);
  pAA += __shfl_xor_sync(0xffffffffu, pAA, 2);
  pBA += __shfl_xor_sync(0xffffffffu, pBA, 1);
  pBA += __shfl_xor_sync(0xffffffffu, pBA, 2);
  pAB += __shfl_xor_sync(0xffffffffu, pAB, 1);
  pAB += __shfl_xor_sync(0xffffffffu, pAB, 2);
  pBB += __shfl_xor_sync(0xffffffffu, pBB, 1);
  pBB += __shfl_xor_sync(0xffffffffu, pBB, 2);
  const float iAA = 1.f / pAA, iBA = 1.f / pBA;
  const float iAB = 1.f / pAB, iBB = 1.f / pBB;

  // ---------------- direct global store (both tiles) ----------------
  {
    float* og = out + (size_t)(blockIdx.x * 2 + bw) * Tn * Hn;
    const int rA = m0A + qr, rB = m0B + qr;
#pragma unroll
    for (int j = 0; j < 8; ++j) {
      int h = j * 8 + qc;
      *reinterpret_cast<float2*>(og + rA * Hn + h) =
          make_float2(accOA[j][0] * iAA, accOA[j][1] * iAA);
      *reinterpret_cast<float2*>(og + (rA + 8) * Hn + h) =
          make_float2(accOA[j][2] * iBA, accOA[j][3] * iBA);
      *reinterpret_cast<float2*>(og + rB * Hn + h) =
          make_float2(accOB[j][0] * iAB, accOB[j][1] * iAB);
      *reinterpret_cast<float2*>(og + (rB + 8) * Hn + h) =
          make_float2(accOB[j][2] * iBB, accOB[j][3] * iBB);
    }
  }
}

}  // namespace

extern "C" void kernel_launch(void* const* d_in, const int* in_sizes, int n_in,
                              void* d_out, int out_size) {
  const float* x  = (const float*)d_in[0];
  const float* Wq = (const float*)d_in[1];
  const float* Wk = (const float*)d_in[2];
  const float* Wv = (const float*)d_in[3];
  float* out = (float*)d_out;

  const int B = in_sizes[0] / (Tn * Cn);   // 4096

  mt_kernel<<<16, 256>>>(Wq, Wk);
  cudaFuncSetAttribute(attn_hmma_kernel,
                       cudaFuncAttributeMaxDynamicSharedMemorySize, SMEM_TOTAL);
  attn_hmma_kernel<<<B / 2, 256, SMEM_TOTAL>>>(x, Wv, out);
}

// round 17
// speedup vs baseline: 1.0711x; 1.0711x over previous
#include <cuda_runtime.h>
#include <cuda_fp16.h>
#include <cstdint>

// Single-head causal attention, B=4096, T=128, C=64, H=64, fp32 I/O.
// Round 15: R13 base (best) + cross-iteration ping-pong in the flash loop:
// S-MMAs of block kb interleave with PV-MMAs of block kb-1 (independent
// chains), so the ex2/pack chain overlaps V-loads instead of gating the
// MMA stream. Single-buffered frags -> register count unchanged vs R13.
// No-max softmax in log2 domain, 1-pass fp16 GEMMs, direct-STG epilogue.

namespace {

constexpr int Tn = 128, Cn = 64, Hn = 64;

// fp16 tiles, 144-byte row stride (conflict-free ldmatrix).
constexpr int OFF_XH = 0;         // 128 x 144 = 18432 (live through flash)
constexpr int OFF_MT = 18432;     // M^T fp16 (9216)
constexpr int OFF_WV = 27648;     // Wv fp16 (9216)
constexpr int SMEM_TOTAL = 36864; // 36KB
// union (disjoint lifetime):
constexpr int OFF_VH = 18432;     // V fp16 (18432) over MT+WV after projections

__device__ float g_MT[64 * 64];   // MT[c'][c] = 0.125*log2e * sum_h Wq[h][c]*Wk[h][c']

__device__ __forceinline__ uint32_t smem_u32(const void* p) {
  uint32_t a;
  asm("{ .reg .u64 t; cvta.to.shared.u64 t, %1; cvt.u32.u64 %0, t; }"
      : "=r"(a) : "l"(p));
  return a;
}
__device__ __forceinline__ float ex2(float x) {
  float r;
  asm("ex2.approx.f32 %0, %1;" : "=f"(r) : "f"(x));
  return r;
}
__device__ __forceinline__ void ldsm4(uint32_t* r, uint32_t a) {
  asm volatile("ldmatrix.sync.aligned.m8n8.x4.shared.b16 {%0,%1,%2,%3}, [%4];"
               : "=r"(r[0]), "=r"(r[1]), "=r"(r[2]), "=r"(r[3]) : "r"(a));
}
__device__ __forceinline__ void ldsm4t(uint32_t* r, uint32_t a) {
  asm volatile("ldmatrix.sync.aligned.m8n8.x4.trans.shared.b16 {%0,%1,%2,%3}, [%4];"
               : "=r"(r[0]), "=r"(r[1]), "=r"(r[2]), "=r"(r[3]) : "r"(a));
}
__device__ __forceinline__ void mma_f16(float* d, const uint32_t* a,
                                        uint32_t b0, uint32_t b1) {
  asm volatile(
      "mma.sync.aligned.m16n8k16.row.col.f32.f16.f16.f32 "
      "{%0,%1,%2,%3}, {%4,%5,%6,%7}, {%8,%9}, {%0,%1,%2,%3};"
      : "+f"(d[0]), "+f"(d[1]), "+f"(d[2]), "+f"(d[3])
      : "r"(a[0]), "r"(a[1]), "r"(a[2]), "r"(a[3]), "r"(b0), "r"(b1));
}
__device__ __forceinline__ uint32_t pack2h(float a, float b) {
  __half2 h2 = __floats2half2_rn(a, b);
  return *reinterpret_cast<uint32_t*>(&h2);
}

// ---- pre-kernel: MT[c'][c] = 0.125*log2e * sum_h Wq[h][c]*Wk[h][c'] ----
__global__ void mt_kernel(const float* __restrict__ Wq,
                          const float* __restrict__ Wk) {
  int i = blockIdx.x * 256 + threadIdx.x;   // 16 blocks x 256 = 4096
  int cp = i >> 6, c = i & 63;
  float s = 0.f;
#pragma unroll 64
  for (int h = 0; h < 64; ++h) s += Wq[h * 64 + c] * Wk[h * 64 + cp];
  g_MT[i] = 0.18033688011112042f * s;   // 0.125 * log2(e)
}

__global__ void __launch_bounds__(256, 2)
attn_hmma_kernel(const float* __restrict__ x,
                 const float* __restrict__ Wv,
                 float* __restrict__ out) {
  extern __shared__ char sm[];
  const uint32_t sb = smem_u32(sm);
  const int tid  = threadIdx.x;
  const int w    = tid >> 5;
  const int lane = tid & 31;
  const int b    = blockIdx.x;
  // SMSP balancing: warps (s, s+4) own row tiles with causal costs summing
  // to 9 on every SMSP: {0,7},{1,6},{2,5},{3,4}.
  const int tile = (w < 4) ? w : (11 - w);
  const int m0   = tile * 16;

  const int arow = lane & 15;
  const int acol = (lane >> 4) * 8;
  const int brow = (lane & 7) + ((lane >= 16) ? 8 : 0);
  const int bk   = ((lane >> 3) & 1) * 8;
  const int trow = (lane & 7) | (((lane >> 3) & 1) << 3);
  const int tcol = (lane >= 16) ? 8 : 0;
  const int qr   = lane >> 2;
  const int qc   = (lane & 3) * 2;

  // ---------------- phase 0: stage x, MT, Wv as fp16 ----------------
  {
    const float4* xg = reinterpret_cast<const float4*>(x + (size_t)b * Tn * Cn);
#pragma unroll
    for (int it = 0; it < 8; ++it) {
      int gi = it * 256 + tid;
      float4 v = xg[gi];
      int t = gi >> 4, c0 = (gi & 15) << 2;
      uint32_t o = (uint32_t)(t * 144 + c0 * 2);
      *reinterpret_cast<uint2*>(sm + OFF_XH + o) =
          make_uint2(pack2h(v.x, v.y), pack2h(v.z, v.w));
    }
    const float4* mg = reinterpret_cast<const float4*>(g_MT);
#pragma unroll
    for (int it = 0; it < 4; ++it) {
      int gi = it * 256 + tid;
      float4 v = mg[gi];
      int h = gi >> 4, c0 = (gi & 15) << 2;
      uint32_t o = (uint32_t)(h * 144 + c0 * 2);
      *reinterpret_cast<uint2*>(sm + OFF_MT + o) =
          make_uint2(pack2h(v.x, v.y), pack2h(v.z, v.w));
    }
    const float4* wg = reinterpret_cast<const float4*>(Wv);
#pragma unroll
    for (int it = 0; it < 4; ++it) {
      int gi = it * 256 + tid;
      float4 v = wg[gi];
      int h = gi >> 4, c0 = (gi & 15) << 2;
      uint32_t o = (uint32_t)(h * 144 + c0 * 2);
      *reinterpret_cast<uint2*>(sm + OFF_WV + o) =
          make_uint2(pack2h(v.x, v.y), pack2h(v.z, v.w));
    }
  }
  __syncthreads();

  // ---------------- x A-frags resident in registers ----------------
  uint32_t xh[4][4];
#pragma unroll
  for (int kk = 0; kk < 4; ++kk) {
    uint32_t o = (uint32_t)((m0 + arow) * 144 + (kk * 16 + acol) * 2);
    ldsm4(xh[kk], sb + OFF_XH + o);
  }

  float acc[8][4];
  // 1-pass GEMM: A = xh, B = fp16 weights. 32 MMAs.
  auto proj1 = [&](int wbase) {
#pragma unroll
    for (int j = 0; j < 8; ++j)
#pragma unroll
      for (int e = 0; e < 4; ++e) acc[j][e] = 0.f;
#pragma unroll
    for (int kk = 0; kk < 4; ++kk) {
#pragma unroll
      for (int up = 0; up < 2; ++up) {
        uint32_t bh0[4], bh1[4];
        uint32_t o0 = (uint32_t)((16 * (2 * up)     + brow) * 144 + (kk * 16 + bk) * 2);
        uint32_t o1 = (uint32_t)((16 * (2 * up + 1) + brow) * 144 + (kk * 16 + bk) * 2);
        ldsm4(bh0, sb + wbase + o0);
        ldsm4(bh1, sb + wbase + o1);
        mma_f16(acc[4 * up],     xh[kk], bh0[0], bh0[1]);
        mma_f16(acc[4 * up + 1], xh[kk], bh0[2], bh0[3]);
        mma_f16(acc[4 * up + 2], xh[kk], bh1[0], bh1[1]);
        mma_f16(acc[4 * up + 3], xh[kk], bh1[2], bh1[3]);
      }
    }
  };

  // q = x @ MT^T (scale+log2e folded) -> A-frags fp16
  uint32_t qh[4][4];
  proj1(OFF_MT);
#pragma unroll
  for (int kk = 0; kk < 4; ++kk) {
    qh[kk][0] = pack2h(acc[2 * kk][0],     acc[2 * kk][1]);
    qh[kk][1] = pack2h(acc[2 * kk][2],     acc[2 * kk][3]);
    qh[kk][2] = pack2h(acc[2 * kk + 1][0], acc[2 * kk + 1][1]);
    qh[kk][3] = pack2h(acc[2 * kk + 1][2], acc[2 * kk + 1][3]);
  }
  // V = x @ Wv^T
  proj1(OFF_WV);
  __syncthreads();          // all MT/WV reads complete before overwrite
  {                         // spill V over MT+WV region
    const int sA = m0 + qr, sB = sA + 8;
#pragma unroll
    for (int j = 0; j < 8; ++j) {
      int h = j * 8 + qc;
      *reinterpret_cast<uint32_t*>(sm + OFF_VH + sA * 144 + h * 2) =
          pack2h(acc[j][0], acc[j][1]);
      *reinterpret_cast<uint32_t*>(sm + OFF_VH + sB * 144 + h * 2) =
          pack2h(acc[j][2], acc[j][3]);
    }
  }
  __syncthreads();          // V visible

  // ---------------- flash loop (ping-pong S/PV across blocks) --------------
  const int rowA = m0 + qr, rowB = rowA + 8;
  float accO[8][4];
#pragma unroll
  for (int j = 0; j < 8; ++j)
#pragma unroll
    for (int e = 0; e < 4; ++e) accO[j][e] = 0.f;
  float pA = 0.f, pB = 0.f;   // running (unnormalized) row sums

  uint32_t xo = sb + OFF_XH + (uint32_t)(brow * 144 + bk * 2);
  uint32_t vo = sb + OFF_VH + (uint32_t)(trow * 144 + tcol * 2);

  uint32_t b0[4], b1[4], b2[4], b3[4], v0[4], v1[4], v2[4], v3[4];
  float sf[2][4];
  uint32_t ph[4];

  auto load_b = [&]() {
    ldsm4(b0, xo); ldsm4(b1, xo + 32); ldsm4(b2, xo + 64); ldsm4(b3, xo + 96);
  };
  auto load_v = [&]() {
    ldsm4t(v0, vo); ldsm4t(v1, vo + 32); ldsm4t(v2, vo + 64); ldsm4t(v3, vo + 96);
  };
  auto do_s = [&]() {
#pragma unroll
    for (int j = 0; j < 2; ++j)
#pragma unroll
      for (int e = 0; e < 4; ++e) sf[j][e] = 0.f;
    mma_f16(sf[0], qh[0], b0[0], b0[1]);
    mma_f16(sf[1], qh[0], b0[2], b0[3]);
    mma_f16(sf[0], qh[1], b1[0], b1[1]);
    mma_f16(sf[1], qh[1], b1[2], b1[3]);
    mma_f16(sf[0], qh[2], b2[0], b2[1]);
    mma_f16(sf[1], qh[2], b2[2], b2[3]);
    mma_f16(sf[0], qh[3], b3[0], b3[1]);
    mma_f16(sf[1], qh[3], b3[2], b3[3]);
  };
  // S(kb) on fresh b interleaved with PV(kb-1) on held v/ph: independent
  // chains, fills the MMA stream while the previous exp chain drains.
  auto do_s_pv = [&]() {
#pragma unroll
    for (int j = 0; j < 2; ++j)
#pragma unroll
      for (int e = 0; e < 4; ++e) sf[j][e] = 0.f;
    mma_f16(sf[0],   qh[0], b0[0], b0[1]);
    mma_f16(accO[0], ph,    v0[0], v0[1]);
    mma_f16(sf[1],   qh[0], b0[2], b0[3]);
    mma_f16(accO[1], ph,    v0[2], v0[3]);
    mma_f16(sf[0],   qh[1], b1[0], b1[1]);
    mma_f16(accO[2], ph,    v1[0], v1[1]);
    mma_f16(sf[1],   qh[1], b1[2], b1[3]);
    mma_f16(accO[3], ph,    v1[2], v1[3]);
    mma_f16(sf[0],   qh[2], b2[0], b2[1]);
    mma_f16(accO[4], ph,    v2[0], v2[1]);
    mma_f16(sf[1],   qh[2], b2[2], b2[3]);
    mma_f16(accO[5], ph,    v2[2], v2[3]);
    mma_f16(sf[0],   qh[3], b3[0], b3[1]);
    mma_f16(accO[6], ph,    v3[0], v3[1]);
    mma_f16(sf[1],   qh[3], b3[2], b3[3]);
    mma_f16(accO[7], ph,    v3[2], v3[3]);
  };
  auto do_exp_full = [&]() {
    float e00 = ex2(sf[0][0]), e01 = ex2(sf[0][1]);
    float e10 = ex2(sf[1][0]), e11 = ex2(sf[1][1]);
    float e02 = ex2(sf[0][2]), e03 = ex2(sf[0][3]);
    float e12 = ex2(sf[1][2]), e13 = ex2(sf[1][3]);
    pA += e00 + e01 + e10 + e11;
    pB += e02 + e03 + e12 + e13;
    ph[0] = pack2h(e00, e01); ph[1] = pack2h(e02, e03);
    ph[2] = pack2h(e10, e11); ph[3] = pack2h(e12, e13);
  };
  auto do_exp_diag = [&]() {
    float e00 = (qc     <= qr)     ? ex2(sf[0][0]) : 0.f;
    float e01 = (qc + 1 <= qr)     ? ex2(sf[0][1]) : 0.f;
    float e10 = (8 + qc     <= qr) ? ex2(sf[1][0]) : 0.f;
    float e11 = (8 + qc + 1 <= qr) ? ex2(sf[1][1]) : 0.f;
    float e02 = (qc     <= qr + 8) ? ex2(sf[0][2]) : 0.f;
    float e03 = (qc + 1 <= qr + 8) ? ex2(sf[0][3]) : 0.f;
    float e12 = (8 + qc     <= qr + 8) ? ex2(sf[1][2]) : 0.f;
    float e13 = (8 + qc + 1 <= qr + 8) ? ex2(sf[1][3]) : 0.f;
    pA += e00 + e01 + e10 + e11;
    pB += e02 + e03 + e12 + e13;
    ph[0] = pack2h(e00, e01); ph[1] = pack2h(e02, e03);
    ph[2] = pack2h(e10, e11); ph[3] = pack2h(e12, e13);
  };

  // prologue: block 0
  load_b();
  do_s();
  if (tile == 0) do_exp_diag(); else do_exp_full();
  load_v();

  // steady state: S(kb) + PV(kb-1) interleaved
  for (int kb = 1; kb <= tile; ++kb) {
    xo += 2304;
    load_b();
    do_s_pv();
    vo += 2304;
    load_v();
    if (kb == tile) do_exp_diag(); else do_exp_full();
  }

  // epilogue: PV(tile)
  mma_f16(accO[0], ph, v0[0], v0[1]);
  mma_f16(accO[1], ph, v0[2], v0[3]);
  mma_f16(accO[2], ph, v1[0], v1[1]);
  mma_f16(accO[3], ph, v1[2], v1[3]);
  mma_f16(accO[4], ph, v2[0], v2[1]);
  mma_f16(accO[5], ph, v2[2], v2[3]);
  mma_f16(accO[6], ph, v3[0], v3[1]);
  mma_f16(accO[7], ph, v3[2], v3[3]);

  pA += __shfl_xor_sync(0xffffffffu, pA, 1);
  pA += __shfl_xor_sync(0xffffffffu, pA, 2);
  pB += __shfl_xor_sync(0xffffffffu, pB, 1);
  pB += __shfl_xor_sync(0xffffffffu, pB, 2);
  const float invA = 1.f / pA, invB = 1.f / pB;

  // ---------------- direct global store (full 32B sectors per quad) --------
  {
    float* og = out + (size_t)b * Tn * Hn;
#pragma unroll
    for (int j = 0; j < 8; ++j) {
      int h = j * 8 + qc;
      *reinterpret_cast<float2*>(og + rowA * Hn + h) =
          make_float2(accO[j][0] * invA, accO[j][1] * invA);
      *reinterpret_cast<float2*>(og + rowB * Hn + h) =
          make_float2(accO[j][2] * invB, accO[j][3] * invB);
    }
  }
}

}  // namespace

extern "C" void kernel_launch(void* const* d_in, const int* in_sizes, int n_in,
                              void* d_out, int out_size) {
  const float* x  = (const float*)d_in[0];
  const float* Wq = (const float*)d_in[1];
  const float* Wk = (const float*)d_in[2];
  const float* Wv = (const float*)d_in[3];
  float* out = (float*)d_out;

  const int B = in_sizes[0] / (Tn * Cn);   // 4096

  mt_kernel<<<16, 256>>>(Wq, Wk);
  cudaFuncSetAttribute(attn_hmma_kernel,
                       cudaFuncAttributeMaxDynamicSharedMemorySize, SMEM_TOTAL);
  attn_hmma_kernel<<<B, 256, SMEM_TOTAL>>>(x, Wv, out);
}